// round 9
// baseline (speedup 1.0000x reference)
#include <cuda_runtime.h>
#include <cuda_bf16.h>
#include <cstdint>

#define ST 144                  // row stride bytes (72 bf16): bank-rotating, 16B-aligned
// per-graph tile regions: GB(gi) = gi*27648
#define ADJ_R 0                 // adjacency -> h3 hi
#define XH_R  9216              // X^T hi / T hi / h3 lo
#define XL_R  18432             // X^T lo / T lo
#define WH_O  55296             // shared W^T hi (scratch pre-loop; head: Wf1^T half hi)
#define WL_O  64512             // shared W^T lo
#define DINV_O 73728            // +gi*256
#define BW_O   74240            // 512B: bias (layers) / wf2 (head)
#define U_O    74752            // +gi*512
#define MP_O   75776            // +gi*512: mean(256)+h3s(256) -> part(512) overlay
#define SMEM_BYTES 76800

static __device__ __align__(16) unsigned char g_WT[3][2][9216];   // W_L^T [n][k] hi/lo
static __device__ __align__(16) unsigned char g_Wf1T[2][18432];   // Wf1_dev^T [m][k] hi/lo

__device__ __forceinline__ uint32_t smem_u32(const void* p) {
    uint32_t a;
    asm("{ .reg .u64 t; cvta.to.shared.u64 t, %1; cvt.u32.u64 %0, t; }" : "=r"(a) : "l"(p));
    return a;
}
__device__ __forceinline__ void ldsm4(uint32_t addr, uint32_t* r) {
    asm volatile("ldmatrix.sync.aligned.m8n8.x4.shared.b16 {%0,%1,%2,%3}, [%4];"
                 : "=r"(r[0]), "=r"(r[1]), "=r"(r[2]), "=r"(r[3]) : "r"(addr));
}
__device__ __forceinline__ void mma16816(float* d, const uint32_t* a, const uint32_t* b) {
    asm volatile("mma.sync.aligned.m16n8k16.row.col.f32.bf16.bf16.f32 "
        "{%0,%1,%2,%3}, {%4,%5,%6,%7}, {%8,%9}, {%0,%1,%2,%3};"
        : "+f"(d[0]), "+f"(d[1]), "+f"(d[2]), "+f"(d[3])
        : "r"(a[0]), "r"(a[1]), "r"(a[2]), "r"(a[3]), "r"(b[0]), "r"(b[1]));
}
__device__ __forceinline__ void sp1(float v, uint16_t& h, uint16_t& l) {
    __nv_bfloat16 hb = __float2bfloat16(v);
    __nv_bfloat16 lb = __float2bfloat16(v - __bfloat162float(hb));
    h = __bfloat16_as_ushort(hb); l = __bfloat16_as_ushort(lb);
}
__device__ __forceinline__ uint32_t sp2(float a, float b, uint32_t& lo) {
    uint16_t ah, al, bh, bl; sp1(a, ah, al); sp1(b, bh, bl);
    lo = (uint32_t)al | ((uint32_t)bl << 16);
    return (uint32_t)ah | ((uint32_t)bh << 16);
}
__device__ __forceinline__ float rdbf(const unsigned char* sm, int off, int r, int c) {
    return __bfloat162float(*(const __nv_bfloat16*)(sm + off + r * ST + c * 2));
}
// D(32x32) += A_img[m0..+31][k] @ B_img[n0..+31][k]^T over K=64
// acc[mt*4 + nt][4]: rows m0+mt*16+g(+8), cols n0+nt*8+c0b(+1)
__device__ __forceinline__ void gprod32(uint32_t aB, uint32_t bB, int lane, float (*acc)[4]) {
    const int arow = lane & 15, acol = (lane >> 4) << 3;
    const int brow = (lane & 7) + ((lane & 16) >> 1), bcol = lane & 8;
    #pragma unroll
    for (int kk = 0; kk < 64; kk += 16) {
        uint32_t a0[4], a1[4];
        ldsm4(aB + arow * ST + (kk + acol) * 2, a0);
        ldsm4(aB + (16 + arow) * ST + (kk + acol) * 2, a1);
        #pragma unroll
        for (int nt = 0; nt < 2; nt++) {
            uint32_t bf[4]; ldsm4(bB + (nt * 16 + brow) * ST + (kk + bcol) * 2, bf);
            mma16816(acc[nt * 2],     a0, bf);
            mma16816(acc[nt * 2 + 1], a0, bf + 2);
            mma16816(acc[4 + nt * 2],     a1, bf);
            mma16816(acc[4 + nt * 2 + 1], a1, bf + 2);
        }
    }
}

__global__ void pgcn_prep(const float* __restrict__ W1, const float* __restrict__ W2,
                          const float* __restrict__ W3, const float* __restrict__ Wf1) {
    const float* Ws[3] = {W1, W2, W3};
    int gt = blockIdx.x * blockDim.x + threadIdx.x, nth = gridDim.x * blockDim.x;
    for (int L = 0; L < 3; L++)
        for (int i = gt; i < 4096; i += nth) {
            int n = i >> 6, k = i & 63;
            uint16_t h, l; sp1(Ws[L][k * 64 + n], h, l);
            *(uint16_t*)(g_WT[L][0] + n * ST + k * 2) = h;
            *(uint16_t*)(g_WT[L][1] + n * ST + k * 2) = l;
        }
    for (int i = gt; i < 8192; i += nth) {
        int m = i >> 6, k = i & 63;
        uint16_t h, l; sp1(Wf1[k * 128 + m], h, l);
        *(uint16_t*)(g_Wf1T[0] + m * ST + k * 2) = h;
        *(uint16_t*)(g_Wf1T[1] + m * ST + k * 2) = l;
    }
}

__global__ __launch_bounds__(256, 3)
void pgcn_main(const float* __restrict__ dev_obs, const float* __restrict__ srv_obs,
               const float* __restrict__ adj,
               const float* __restrict__ W_dev, const float* __restrict__ b_dev,
               const float* __restrict__ W_srv, const float* __restrict__ b_srv,
               const float* __restrict__ b1, const float* __restrict__ b2,
               const float* __restrict__ b3,
               const float* __restrict__ Wf1, const float* __restrict__ bf1,
               const float* __restrict__ Wf2, const float* __restrict__ bf2,
               float* __restrict__ out)
{
    extern __shared__ __align__(16) unsigned char sm[];
    const uint32_t sb = smem_u32(sm);
    const int tid = threadIdx.x, lane = tid & 31, wid = tid >> 5;
    const int b0 = blockIdx.x * 2;
    const int gi = wid >> 2, w4 = wid & 3;                 // graph, warp-in-graph
    const int m0 = (w4 & 1) * 32, n0 = (w4 >> 1) * 32;     // 2x2 grid of 32x32 tiles
    const int g = lane >> 2, c0b = (lane & 3) * 2;
    const uint32_t GB = (uint32_t)gi * 27648u;
    float* s_dinv = (float*)(sm + DINV_O + gi * 256);      // this graph's dinv
    float* s_bw   = (float*)(sm + BW_O);                   // bias / wf2
    float* s_u    = (float*)(sm + U_O + gi * 512);
    float* s_mp   = (float*)(sm + MP_O + gi * 512);        // mean|h3s -> part

    // ---- scratch: ew in WH; obs per graph in WL; masks in WH tail ----
    float* s_ew = (float*)(sm + WH_O);
    for (int i = tid; i < 896; i += 256) s_ew[i] = W_dev[i];
    if (tid < 192) s_ew[896 + tid] = W_srv[tid];
    for (int i = tid; i < 882; i += 256) {
        ((float*)(sm + WL_O))[i]       = dev_obs[(size_t)b0 * 882 + i];
        ((float*)(sm + WL_O + 3584))[i] = dev_obs[(size_t)(b0 + 1) * 882 + i];
    }
    if (tid < 3) {
        ((float*)(sm + WL_O))[882 + tid]        = srv_obs[b0 * 3 + tid];
        ((float*)(sm + WL_O + 3584))[882 + tid] = srv_obs[(b0 + 1) * 3 + tid];
    }
    for (int r = wid; r < 128; r += 8) {
        int gr = r >> 6, rr = r & 63;
        const float* ar = adj + (size_t)(b0 + gr) * 4096 + rr * 64;
        unsigned a0 = __ballot_sync(0xffffffffu, ar[lane] != 0.0f);
        unsigned a1 = __ballot_sync(0xffffffffu, ar[32 + lane] != 0.0f);
        if (lane == 0) {
            ((unsigned*)(sm + WH_O + 4608 + gr * 512))[rr] = a0;
            ((unsigned*)(sm + WH_O + 4608 + gr * 512))[64 + rr] = a1;
            ((float*)(sm + DINV_O + gr * 256))[rr] =
                rsqrtf(fmaxf((float)(__popc(a0) + __popc(a1)), 1.0f));
        }
    }
    __syncthreads();

    // ---- adjacency bf16 tiles + embedding -> X^T hi/lo ----
    for (int i = tid; i < 1024; i += 256) {
        int g2 = i >> 9, rr = (i >> 3) & 63, chk = i & 7;
        const unsigned* mk = (const unsigned*)(sm + WH_O + 4608 + g2 * 512);
        unsigned byte8 = ((chk < 4 ? mk[rr] : mk[64 + rr]) >> ((chk & 3) * 8)) & 0xFF;
        uint4 v; uint32_t* vp = (uint32_t*)&v;
        #pragma unroll
        for (int j = 0; j < 4; j++) {
            unsigned b2 = (byte8 >> (2 * j)) & 3;
            vp[j] = ((b2 & 1) ? 0x3F80u : 0u) | ((b2 & 2) ? 0x3F800000u : 0u);
        }
        *(uint4*)(sm + g2 * 27648 + ADJ_R + rr * ST + chk * 16) = v;
    }
    for (int it = 0; it < 16; it++) {
        int idx = tid + it * 256;                 // [0, 4096)
        int g2 = idx >> 11, rem = idx & 2047;
        int c = rem & 63, np = (rem >> 6) * 2;
        const float* ob = (const float*)(sm + WL_O + g2 * 3584);
        const float* dv = (const float*)(sm + DINV_O + g2 * 256);
        float e[2];
        #pragma unroll
        for (int q = 0; q < 2; q++) {
            int n = np + q; float acc;
            if (n < 63) {
                acc = b_dev[c];
                const float* o = ob + n * 14;
                #pragma unroll
                for (int k = 0; k < 14; k++) acc = fmaf(o[k], s_ew[k * 64 + c], acc);
            } else {
                acc = b_srv[c];
                #pragma unroll
                for (int k = 0; k < 3; k++) acc = fmaf(ob[882 + k], s_ew[896 + k * 64 + c], acc);
            }
            e[q] = fmaxf(acc, 0.0f) * dv[n];
        }
        uint32_t lo, hi = sp2(e[0], e[1], lo);
        *(uint32_t*)(sm + g2 * 27648 + XH_R + c * ST + np * 2) = hi;
        *(uint32_t*)(sm + g2 * 27648 + XL_R + c * ST + np * 2) = lo;
    }
    __syncthreads();

    // ---- 3 GCN layers ----
    #pragma unroll 1
    for (int L = 0; L < 3; L++) {
        {   // stage shared W^T hi/lo + bias
            const uint4* wh = (const uint4*)g_WT[L][0];
            const uint4* wl = (const uint4*)g_WT[L][1];
            for (int i = tid; i < 576; i += 256) {
                ((uint4*)(sm + WH_O))[i] = wh[i];
                ((uint4*)(sm + WL_O))[i] = wl[i];
            }
            const float* bl = (L == 0) ? b1 : (L == 1) ? b2 : b3;
            if (tid < 64) s_bw[tid] = bl[tid];
        }
        // aggregation: D[r][c] = Adj @ X^T(hi)ᵀ + Adj @ X^T(lo)ᵀ
        float acc[8][4];
        #pragma unroll
        for (int i = 0; i < 8; i++) { acc[i][0]=acc[i][1]=acc[i][2]=acc[i][3]=0.f; }
        gprod32(sb + GB + ADJ_R + m0 * ST, sb + GB + XH_R + n0 * ST, lane, acc);
        gprod32(sb + GB + ADJ_R + m0 * ST, sb + GB + XL_R + n0 * ST, lane, acc);
        __syncthreads();   // X reads done; W staged

        // epi1: T[r][c] = dinv[r]*D -> overwrite XH/XL
        #pragma unroll
        for (int mt = 0; mt < 2; mt++) {
            int r0 = m0 + mt * 16 + g, r1 = r0 + 8;
            float d0 = s_dinv[r0], d1 = s_dinv[r1];
            #pragma unroll
            for (int nt = 0; nt < 4; nt++) {
                int c0 = n0 + nt * 8 + c0b;
                float* a4 = acc[mt * 4 + nt];
                uint32_t lo, hi;
                hi = sp2(a4[0] * d0, a4[1] * d0, lo);
                *(uint32_t*)(sm + GB + XH_R + r0 * ST + c0 * 2) = hi;
                *(uint32_t*)(sm + GB + XL_R + r0 * ST + c0 * 2) = lo;
                hi = sp2(a4[2] * d1, a4[3] * d1, lo);
                *(uint32_t*)(sm + GB + XH_R + r1 * ST + c0 * 2) = hi;
                *(uint32_t*)(sm + GB + XL_R + r1 * ST + c0 * 2) = lo;
            }
        }
        __syncthreads();   // T visible

        #pragma unroll
        for (int i = 0; i < 8; i++) { acc[i][0]=acc[i][1]=acc[i][2]=acc[i][3]=0.f; }
        if (L < 2) {
            // gemm (transposed out): D[c][r] = Wᵀ @ Tᵀ
            gprod32(sb + WH_O + m0 * ST, sb + GB + XH_R + n0 * ST, lane, acc);
            gprod32(sb + WH_O + m0 * ST, sb + GB + XL_R + n0 * ST, lane, acc);
            gprod32(sb + WL_O + m0 * ST, sb + GB + XH_R + n0 * ST, lane, acc);
            __syncthreads();   // T reads done
            // epi2: X^T[c][r] = relu(D + b[c]) * dinv[r]
            #pragma unroll
            for (int mt = 0; mt < 2; mt++) {
                int cA0 = m0 + mt * 16 + g, cA1 = cA0 + 8;
                float bA0 = s_bw[cA0], bA1 = s_bw[cA1];
                #pragma unroll
                for (int nt = 0; nt < 4; nt++) {
                    int r0 = n0 + nt * 8 + c0b;
                    float da = s_dinv[r0], db = s_dinv[r0 + 1];
                    float* a4 = acc[mt * 4 + nt];
                    uint32_t lo, hi;
                    hi = sp2(fmaxf(a4[0] + bA0, 0.f) * da, fmaxf(a4[1] + bA0, 0.f) * db, lo);
                    *(uint32_t*)(sm + GB + XH_R + cA0 * ST + r0 * 2) = hi;
                    *(uint32_t*)(sm + GB + XL_R + cA0 * ST + r0 * 2) = lo;
                    hi = sp2(fmaxf(a4[2] + bA1, 0.f) * da, fmaxf(a4[3] + bA1, 0.f) * db, lo);
                    *(uint32_t*)(sm + GB + XH_R + cA1 * ST + r0 * 2) = hi;
                    *(uint32_t*)(sm + GB + XL_R + cA1 * ST + r0 * 2) = lo;
                }
            }
        } else {
            // gemm3: D[r][c] = T @ Wᵀ  (node-major h3)
            gprod32(sb + GB + XH_R + m0 * ST, sb + WH_O + n0 * ST, lane, acc);
            gprod32(sb + GB + XL_R + m0 * ST, sb + WH_O + n0 * ST, lane, acc);
            gprod32(sb + GB + XH_R + m0 * ST, sb + WL_O + n0 * ST, lane, acc);
            __syncthreads();
            // epi3: h3 = relu(D + b[c]); hi->ADJ, lo->XH
            #pragma unroll
            for (int mt = 0; mt < 2; mt++) {
                int r0 = m0 + mt * 16 + g, r1 = r0 + 8;
                #pragma unroll
                for (int nt = 0; nt < 4; nt++) {
                    int c0 = n0 + nt * 8 + c0b;
                    float b0v = s_bw[c0], b1v = s_bw[c0 + 1];
                    float* a4 = acc[mt * 4 + nt];
                    uint32_t lo, hi;
                    hi = sp2(fmaxf(a4[0] + b0v, 0.f), fmaxf(a4[1] + b1v, 0.f), lo);
                    *(uint32_t*)(sm + GB + ADJ_R + r0 * ST + c0 * 2) = hi;
                    *(uint32_t*)(sm + GB + XH_R + r0 * ST + c0 * 2) = lo;
                    hi = sp2(fmaxf(a4[2] + b0v, 0.f), fmaxf(a4[3] + b1v, 0.f), lo);
                    *(uint32_t*)(sm + GB + ADJ_R + r1 * ST + c0 * 2) = hi;
                    *(uint32_t*)(sm + GB + XH_R + r1 * ST + c0 * 2) = lo;
                }
            }
        }
        __syncthreads();
    }

    // ---- head prep: mean + server row (tid<128) || stage Wf1^T half0 + wf2 ----
    if (tid < 128) {
        int g2 = tid >> 6, c = tid & 63;
        const unsigned char* gbp = sm + g2 * 27648;
        float s = 0.0f;
        for (int r = 0; r < 63; r++) s += rdbf(gbp, ADJ_R, r, c) + rdbf(gbp, XH_R, r, c);
        float* mp = (float*)(sm + MP_O + g2 * 512);
        mp[c] = s * (1.0f / 63.0f);                                   // mean
        mp[64 + c] = rdbf(gbp, ADJ_R, 63, c) + rdbf(gbp, XH_R, 63, c); // h3 server
    } else {
        const uint4* hh = (const uint4*)g_Wf1T[0];
        const uint4* hl = (const uint4*)g_Wf1T[1];
        for (int i = tid - 128; i < 576; i += 128) {
            ((uint4*)(sm + WH_O))[i] = hh[i];
            ((uint4*)(sm + WL_O))[i] = hl[i];
        }
        if (tid - 128 < 128) s_bw[tid - 128] = Wf2[tid - 128];  // wf2 (bias dead)
    }
    __syncthreads();
    {   // u_g[m] = bf1 + Wf1_meanᵀ mean + Wf1_srvᵀ h3srv   (tid>>7 = graph)
        int g2 = tid >> 7, m = tid & 127;
        const float* mp = (const float*)(sm + MP_O + g2 * 512);
        float acc = bf1[m];
        #pragma unroll 4
        for (int k = 0; k < 64; k++) acc = fmaf(mp[k], Wf1[(64 + k) * 128 + m], acc);
        #pragma unroll 4
        for (int k = 0; k < 64; k++) acc = fmaf(mp[64 + k], Wf1[(128 + k) * 128 + m], acc);
        ((float*)(sm + U_O + g2 * 512))[m] = acc;
    }
    __syncthreads();

    // ---- head GEMM: two half passes over Wf1ᵀ ----
    float p[4] = {0.f, 0.f, 0.f, 0.f};   // rows m0+mt*16+g, +8
    #pragma unroll 1
    for (int h = 0; h < 2; h++) {
        if (h == 1) {
            const uint4* hh = (const uint4*)(g_Wf1T[0] + 64 * ST);
            const uint4* hl = (const uint4*)(g_Wf1T[1] + 64 * ST);
            for (int i = tid; i < 576; i += 256) {
                ((uint4*)(sm + WH_O))[i] = hh[i];
                ((uint4*)(sm + WL_O))[i] = hl[i];
            }
            __syncthreads();
        }
        float acc[8][4];
        #pragma unroll
        for (int i = 0; i < 8; i++) { acc[i][0]=acc[i][1]=acc[i][2]=acc[i][3]=0.f; }
        gprod32(sb + GB + ADJ_R + m0 * ST, sb + WH_O + n0 * ST, lane, acc);
        gprod32(sb + GB + XH_R + m0 * ST, sb + WH_O + n0 * ST, lane, acc);
        gprod32(sb + GB + ADJ_R + m0 * ST, sb + WL_O + n0 * ST, lane, acc);
        #pragma unroll
        for (int mt = 0; mt < 2; mt++)
            #pragma unroll
            for (int nt = 0; nt < 4; nt++) {
                int c0 = h * 64 + n0 + nt * 8 + c0b;
                float u0 = s_u[c0], u1 = s_u[c0 + 1], w0 = s_bw[c0], w1 = s_bw[c0 + 1];
                float* a4 = acc[mt * 4 + nt];
                p[mt*2]   = fmaf(fmaxf(a4[0] + u0, 0.f), w0, p[mt*2]);
                p[mt*2]   = fmaf(fmaxf(a4[1] + u1, 0.f), w1, p[mt*2]);
                p[mt*2+1] = fmaf(fmaxf(a4[2] + u0, 0.f), w0, p[mt*2+1]);
                p[mt*2+1] = fmaf(fmaxf(a4[3] + u1, 0.f), w1, p[mt*2+1]);
            }
        __syncthreads();
    }
    #pragma unroll
    for (int i = 0; i < 4; i++) {
        p[i] += __shfl_xor_sync(0xffffffffu, p[i], 1);
        p[i] += __shfl_xor_sync(0xffffffffu, p[i], 2);
    }
    if ((lane & 3) == 0) {               // part[half][row] in MP overlay
        float* part = (float*)(sm + MP_O + gi * 512) + (n0 >> 5) * 64;
        part[m0 + g]      = p[0];
        part[m0 + g + 8]  = p[1];
        part[m0 + 16 + g]     = p[2];
        part[m0 + 16 + g + 8] = p[3];
    }
    __syncthreads();
    if (tid < 128) {
        int g2 = tid >> 6, i = tid & 63;
        const float* part = (const float*)(sm + MP_O + g2 * 512);
        if (i < 63) out[(size_t)(b0 + g2) * 63 + i] = part[i] + part[64 + i] + bf2[0];
    }
}

extern "C" void kernel_launch(void* const* d_in, const int* in_sizes, int n_in,
                              void* d_out, int out_size)
{
    (void)in_sizes; (void)n_in; (void)out_size;
    cudaFuncSetAttribute(pgcn_main, cudaFuncAttributeMaxDynamicSharedMemorySize, SMEM_BYTES);
    pgcn_prep<<<64, 256>>>((const float*)d_in[7], (const float*)d_in[9],
                           (const float*)d_in[11], (const float*)d_in[13]);
    pgcn_main<<<8192, 256, SMEM_BYTES>>>(
        (const float*)d_in[0],  (const float*)d_in[1],  (const float*)d_in[2],
        (const float*)d_in[3],  (const float*)d_in[4],  (const float*)d_in[5],
        (const float*)d_in[6],  (const float*)d_in[8],  (const float*)d_in[10],
        (const float*)d_in[12], (const float*)d_in[13], (const float*)d_in[14],
        (const float*)d_in[15], (const float*)d_in[16], (float*)d_out);
}